// round 1
// baseline (speedup 1.0000x reference)
#include <cuda_runtime.h>

#define EPS 1e-3f

// Problem dims (fixed by reference setup_inputs)
#define B    8
#define CIN  4
#define T0   20
#define S0   24      // input spatial
#define CMID 12
#define T1   18
#define S1   22      // after conv1 (VALID, k=3)
#define COUT 36
#define T2   16
#define S2   20      // after conv2

// h: [B, CMID, T1, S1, S1, S1]
#define H_TOTAL (B*CMID*T1*S1*S1*S1)

__device__ float g_h[H_TOTAL];          // ~73.6 MB scratch
__device__ float g_stats[24];           // [0:12) sum, [12:24) sumsq
__device__ float g_scale[CMID];
__device__ float g_shift[CMID];

// ---------------------------------------------------------------------------
__global__ void zero_stats_k() {
    if (threadIdx.x < 24) g_stats[threadIdx.x] = 0.0f;
}

// ---------------------------------------------------------------------------
// conv1 + ReLU + per-channel sum/sumsq.
// Block = one (b, t_out, d_out) 22x22 output plane, all 12 channels.
// Thread: 2 w-adjacent pixels x 12 channels (24 accumulators). 242 work items,
// blockDim=256 (full warps so shuffle reduction is clean).
__global__ void __launch_bounds__(256) conv1_k(const float* __restrict__ x,
                                               const float* __restrict__ W1,
                                               const float* __restrict__ b1) {
    __shared__ float sp[S0 * S0];     // 576 input-plane floats
    __shared__ float wsm[CMID * 9];   // 108 weights for current (ci,kt,kd)
    __shared__ float sred[24];

    const int d = blockIdx.x;   // 0..21
    const int t = blockIdx.y;   // 0..17
    const int b = blockIdx.z;   // 0..7
    const int tid = threadIdx.x;
    const bool active = tid < 242;
    const int tx = tid % 11;    // w-pair index
    const int ty = tid / 11;    // row 0..21

    float acc[CMID][2];
#pragma unroll
    for (int j = 0; j < CMID; j++) { acc[j][0] = 0.0f; acc[j][1] = 0.0f; }
    if (tid < 24) sred[tid] = 0.0f;

    for (int ci = 0; ci < CIN; ci++) {
        for (int kt = 0; kt < 3; kt++) {
            for (int kd = 0; kd < 3; kd++) {
                // stage input plane x[b][ci][t+kt][d+kd][:][:]
                const int base = ((b * CIN + ci) * T0 + (t + kt)) * (S0 * S0 * S0)
                               + (d + kd) * (S0 * S0);
                for (int i = tid; i < S0 * S0; i += 256) sp[i] = x[base + i];
                if (tid < 108) {
                    const int co = tid / 9, k = tid % 9;
                    wsm[tid] = W1[((co * CIN + ci) * 3 + kt) * 27 + kd * 9 + k];
                }
                __syncthreads();
                if (active) {
                    float px[3][4];
#pragma unroll
                    for (int r = 0; r < 3; r++)
#pragma unroll
                        for (int c = 0; c < 4; c++)
                            px[r][c] = sp[(ty + r) * S0 + 2 * tx + c];
#pragma unroll
                    for (int j = 0; j < CMID; j++) {
                        float w9[9];
#pragma unroll
                        for (int k = 0; k < 9; k++) w9[k] = wsm[j * 9 + k];
#pragma unroll
                        for (int p = 0; p < 2; p++)
#pragma unroll
                            for (int kh = 0; kh < 3; kh++)
#pragma unroll
                                for (int kw = 0; kw < 3; kw++)
                                    acc[j][p] = fmaf(w9[kh * 3 + kw],
                                                     px[kh][p + kw], acc[j][p]);
                    }
                }
                __syncthreads();
            }
        }
    }

    // epilogue: bias + relu + store + channel stats
    const int lane = tid & 31;
#pragma unroll
    for (int j = 0; j < CMID; j++) {
        float v0 = 0.0f, v1 = 0.0f;
        if (active) {
            const float bj = b1[j];
            v0 = fmaxf(acc[j][0] + bj, 0.0f);
            v1 = fmaxf(acc[j][1] + bj, 0.0f);
            const int hb = ((b * CMID + j) * T1 + t) * (S1 * S1 * S1)
                         + d * (S1 * S1) + ty * S1 + 2 * tx;
            g_h[hb]     = v0;
            g_h[hb + 1] = v1;
        }
        float s = v0 + v1;
        float q = v0 * v0 + v1 * v1;
#pragma unroll
        for (int o = 16; o > 0; o >>= 1) {
            s += __shfl_down_sync(0xffffffffu, s, o);
            q += __shfl_down_sync(0xffffffffu, q, o);
        }
        if (lane == 0) {
            atomicAdd(&sred[j], s);
            atomicAdd(&sred[12 + j], q);
        }
    }
    __syncthreads();
    if (tid < 24) atomicAdd(&g_stats[tid], sred[tid]);
}

// ---------------------------------------------------------------------------
__global__ void finalize_k(const float* __restrict__ gamma,
                           const float* __restrict__ beta) {
    const int tid = threadIdx.x;
    if (tid < CMID) {
        const float N = (float)(B * T1 * S1 * S1 * S1);  // 1,533,312
        const float mean = g_stats[tid] / N;
        const float var  = g_stats[12 + tid] / N - mean * mean;
        const float inv  = rsqrtf(var + EPS);
        const float sc   = gamma[tid] * inv;
        g_scale[tid] = sc;
        g_shift[tid] = beta[tid] - mean * sc;
    }
}

// ---------------------------------------------------------------------------
// conv2 + ReLU. Normalization folded into the smem staging of h planes
// (plane value -> v*scale[ci] + shift[ci]).
// Block = one (b, t_out, d_out) 20x20 output plane, 12-channel group (3 groups).
// Thread: 4 w-adjacent pixels x 12 channels (48 accumulators). 100 work items,
// blockDim=128.
__global__ void __launch_bounds__(128) conv2_k(const float* __restrict__ W2,
                                               const float* __restrict__ b2,
                                               float* __restrict__ out) {
    __shared__ float sp[S1 * S1];    // 484
    __shared__ float wsm[108];
    __shared__ float ssc[CMID], ssh[CMID];

    const int d = blockIdx.x;            // 0..19
    const int t = blockIdx.y;            // 0..15
    const int b = blockIdx.z / 3;        // 0..7
    const int g = blockIdx.z % 3;        // channel group
    const int tid = threadIdx.x;
    const bool active = tid < 100;
    const int tx = tid % 5;              // w-quad index
    const int ty = tid / 5;              // row 0..19

    if (tid < CMID) { ssc[tid] = g_scale[tid]; ssh[tid] = g_shift[tid]; }

    float acc[12][4];
#pragma unroll
    for (int j = 0; j < 12; j++)
#pragma unroll
        for (int p = 0; p < 4; p++) acc[j][p] = 0.0f;
    __syncthreads();

    for (int ci = 0; ci < CMID; ci++) {
        const float sc = ssc[ci], sh = ssh[ci];
        for (int kt = 0; kt < 3; kt++) {
            for (int kd = 0; kd < 3; kd++) {
                const int base = ((b * CMID + ci) * T1 + (t + kt)) * (S1 * S1 * S1)
                               + (d + kd) * (S1 * S1);
                for (int i = tid; i < S1 * S1; i += 128)
                    sp[i] = g_h[base + i] * sc + sh;     // fused batchnorm
                if (tid < 108) {
                    const int j = tid / 9, k = tid % 9;
                    wsm[tid] = W2[(((g * 12 + j) * CMID + ci) * 3 + kt) * 27
                                  + kd * 9 + k];
                }
                __syncthreads();
                if (active) {
                    float px[3][6];
#pragma unroll
                    for (int r = 0; r < 3; r++)
#pragma unroll
                        for (int c = 0; c < 6; c++)
                            px[r][c] = sp[(ty + r) * S1 + 4 * tx + c];
#pragma unroll
                    for (int j = 0; j < 12; j++) {
                        float w9[9];
#pragma unroll
                        for (int k = 0; k < 9; k++) w9[k] = wsm[j * 9 + k];
#pragma unroll
                        for (int p = 0; p < 4; p++)
#pragma unroll
                            for (int kh = 0; kh < 3; kh++)
#pragma unroll
                                for (int kw = 0; kw < 3; kw++)
                                    acc[j][p] = fmaf(w9[kh * 3 + kw],
                                                     px[kh][p + kw], acc[j][p]);
                    }
                }
                __syncthreads();
            }
        }
    }

    if (active) {
#pragma unroll
        for (int j = 0; j < 12; j++) {
            const int o = g * 12 + j;
            const float bo = b2[o];
            const int obase = ((b * COUT + o) * T2 + t) * (S2 * S2 * S2)
                            + d * (S2 * S2) + ty * S2 + 4 * tx;
#pragma unroll
            for (int p = 0; p < 4; p++)
                out[obase + p] = fmaxf(acc[j][p] + bo, 0.0f);
        }
    }
}

// ---------------------------------------------------------------------------
extern "C" void kernel_launch(void* const* d_in, const int* in_sizes, int n_in,
                              void* d_out, int out_size) {
    const float* x     = (const float*)d_in[0];
    const float* W1    = (const float*)d_in[1];
    const float* b1    = (const float*)d_in[2];
    const float* gamma = (const float*)d_in[3];
    const float* beta  = (const float*)d_in[4];
    const float* W2    = (const float*)d_in[5];
    const float* b2    = (const float*)d_in[6];
    float* out = (float*)d_out;

    zero_stats_k<<<1, 32>>>();
    conv1_k<<<dim3(S1, T1, B), 256>>>(x, W1, b1);
    finalize_k<<<1, 32>>>(gamma, beta);
    conv2_k<<<dim3(S2, T2, B * 3), 128>>>(W2, b2, out);
}

// round 2
// speedup vs baseline: 1.0847x; 1.0847x over previous
#include <cuda_runtime.h>

#define EPS 1e-3f

#define B    8
#define CIN  4
#define T0   20
#define S0   24
#define CMID 12
#define T1   18
#define S1   22
#define COUT 36
#define T2   16
#define S2   20

#define H_TOTAL (B*CMID*T1*S1*S1*S1)

typedef unsigned long long u64;

__device__ float g_h[H_TOTAL];
__device__ float g_stats[24];
__device__ float g_scale[CMID];
__device__ float g_shift[CMID];

// packed fp32x2 FMA (SASS FFMA2) — lanewise IEEE fp32, lo = first element
__device__ __forceinline__ void ffma2(u64& d, u64 a, u64 b, u64 c) {
    asm("fma.rn.f32x2 %0, %1, %2, %3;" : "=l"(d) : "l"(a), "l"(b), "l"(c));
}
__device__ __forceinline__ u64 pack2(float a, float b) {
    u64 r; asm("mov.b64 %0, {%1, %2};" : "=l"(r) : "f"(a), "f"(b)); return r;
}
__device__ __forceinline__ float lo32(u64 v) { return __uint_as_float((unsigned)v); }
__device__ __forceinline__ float hi32(u64 v) { return __uint_as_float((unsigned)(v >> 32)); }

// ---------------------------------------------------------------------------
__global__ void zero_stats_k() {
    if (threadIdx.x < 24) g_stats[threadIdx.x] = 0.0f;
}

// ---------------------------------------------------------------------------
// conv1 + ReLU + channel stats.  Block = one (b,t,d) 22x22 output plane,
// all 12 channels.  Thread: pixel pair (2 w-adjacent) x 12 channels, packed
// f32x2 accumulators.  Stage: all 9 (kt,kd) subplanes per ci -> 8 barriers.
__global__ void __launch_bounds__(256, 2) conv1_k(const float* __restrict__ x,
                                                  const float* __restrict__ W1,
                                                  const float* __restrict__ b1) {
    __shared__ float  spA[9][S0 * S0];      // 9 x 576
    __shared__ float2 wsm[CMID * 9 * 10];   // dup weights, padded slots of 10
    __shared__ float  sred[24];

    const int d = blockIdx.x;   // 0..21
    const int t = blockIdx.y;   // 0..17
    const int b = blockIdx.z;   // 0..7
    const int tid = threadIdx.x;
    const bool active = tid < 242;
    const int ty = tid / 11;          // row 0..21
    const int c  = 2 * (tid % 11);    // w col of pixel pair

    u64 acc[CMID];
#pragma unroll
    for (int j = 0; j < CMID; j++) acc[j] = 0ull;
    if (tid < 24) sred[tid] = 0.0f;

    for (int ci = 0; ci < CIN; ci++) {
        __syncthreads();
        // ---- stage 9 input subplanes (float4) ----
        for (int i = tid; i < 9 * 144; i += 256) {
            const int s = i / 144, q = i - s * 144;
            const int kt = s / 3, kd = s - kt * 3;
            const int base = ((b * CIN + ci) * T0 + (t + kt)) * (S0 * S0 * S0)
                           + (d + kd) * (S0 * S0);
            ((float4*)spA[s])[q] = __ldg((const float4*)(x + base) + q);
        }
        // ---- stage duplicated weights ----
        for (int i = tid; i < CMID * 81; i += 256) {
            const int j = i / 81, r = i - j * 81;
            const int s = r / 9, tap = r - s * 9;
            const float w = W1[(j * CIN + ci) * 81 + r];
            wsm[(j * 9 + s) * 10 + tap] = make_float2(w, w);
        }
        __syncthreads();

        if (active) {
#pragma unroll
            for (int s = 0; s < 9; s++) {
                u64 pa0[3], pa1[3], pb[3];
#pragma unroll
                for (int kh = 0; kh < 3; kh++) {
                    const float2* rp = (const float2*)&spA[s][(ty + kh) * S0 + c];
                    const float2 f0 = rp[0], f1 = rp[1];
                    pa0[kh] = pack2(f0.x, f0.y);
                    pa1[kh] = pack2(f1.x, f1.y);
                    pb[kh]  = pack2(f0.y, f1.x);
                }
#pragma unroll
                for (int j = 0; j < CMID; j++) {
                    const float2* wb = &wsm[(j * 9 + s) * 10];
                    const ulonglong2 w01 = *(const ulonglong2*)(wb + 0);
                    const ulonglong2 w23 = *(const ulonglong2*)(wb + 2);
                    const ulonglong2 w45 = *(const ulonglong2*)(wb + 4);
                    const ulonglong2 w67 = *(const ulonglong2*)(wb + 6);
                    const u64 w8 = *(const u64*)(wb + 8);
                    const u64 w[9] = {w01.x, w01.y, w23.x, w23.y,
                                      w45.x, w45.y, w67.x, w67.y, w8};
#pragma unroll
                    for (int kh = 0; kh < 3; kh++) {
                        ffma2(acc[j], w[kh * 3 + 0], pa0[kh], acc[j]);
                        ffma2(acc[j], w[kh * 3 + 1], pb[kh],  acc[j]);
                        ffma2(acc[j], w[kh * 3 + 2], pa1[kh], acc[j]);
                    }
                }
            }
        }
    }

    // ---- epilogue: bias + relu + store + stats ----
    const int lane = tid & 31;
#pragma unroll
    for (int j = 0; j < CMID; j++) {
        float v0 = 0.0f, v1 = 0.0f;
        if (active) {
            const float bj = b1[j];
            v0 = fmaxf(lo32(acc[j]) + bj, 0.0f);
            v1 = fmaxf(hi32(acc[j]) + bj, 0.0f);
            const int hb = ((b * CMID + j) * T1 + t) * (S1 * S1 * S1)
                         + d * (S1 * S1) + ty * S1 + c;
            g_h[hb]     = v0;
            g_h[hb + 1] = v1;
        }
        float s = v0 + v1;
        float q = v0 * v0 + v1 * v1;
#pragma unroll
        for (int o = 16; o > 0; o >>= 1) {
            s += __shfl_down_sync(0xffffffffu, s, o);
            q += __shfl_down_sync(0xffffffffu, q, o);
        }
        if (lane == 0) {
            atomicAdd(&sred[j], s);
            atomicAdd(&sred[12 + j], q);
        }
    }
    __syncthreads();
    if (tid < 24) atomicAdd(&g_stats[tid], sred[tid]);
}

// ---------------------------------------------------------------------------
__global__ void finalize_k(const float* __restrict__ gamma,
                           const float* __restrict__ beta) {
    const int tid = threadIdx.x;
    if (tid < CMID) {
        const float N = (float)(B * T1 * S1 * S1 * S1);
        const float mean = g_stats[tid] / N;
        const float var  = g_stats[12 + tid] / N - mean * mean;
        const float inv  = rsqrtf(var + EPS);
        const float sc   = gamma[tid] * inv;
        g_scale[tid] = sc;
        g_shift[tid] = beta[tid] - mean * sc;
    }
}

// ---------------------------------------------------------------------------
// conv2 + ReLU, batchnorm folded into staging.  Block = (b,t,d) 20x20 output
// plane, 12-channel group.  Thread: 4 pixels (2 f32x2 pairs) x 12 channels.
__global__ void __launch_bounds__(128, 4) conv2_k(const float* __restrict__ W2,
                                                  const float* __restrict__ b2,
                                                  float* __restrict__ out) {
    __shared__ float  spA[9][S1 * S1];      // 9 x 484
    __shared__ float2 wsm[12 * 9 * 10];

    const int d = blockIdx.x;            // 0..19
    const int t = blockIdx.y;            // 0..15
    const int b = blockIdx.z / 3;
    const int g = blockIdx.z % 3;
    const int tid = threadIdx.x;
    const bool active = tid < 100;
    const int ty = tid / 5;              // row 0..19
    const int c  = 4 * (tid % 5);        // w col of pixel quad

    u64 acc0[12], acc1[12];
#pragma unroll
    for (int j = 0; j < 12; j++) { acc0[j] = 0ull; acc1[j] = 0ull; }

    for (int ci = 0; ci < CMID; ci++) {
        __syncthreads();
        const float sc = g_scale[ci];
        const float sh = g_shift[ci];
        // ---- stage 9 h subplanes with fused batchnorm affine ----
        for (int i = tid; i < 9 * 121; i += 128) {
            const int s = i / 121, q = i - s * 121;
            const int kt = s / 3, kd = s - kt * 3;
            const int base = ((b * CMID + ci) * T1 + (t + kt)) * (S1 * S1 * S1)
                           + (d + kd) * (S1 * S1);
            float4 v = __ldg((const float4*)(g_h + base) + q);
            v.x = fmaf(v.x, sc, sh);
            v.y = fmaf(v.y, sc, sh);
            v.z = fmaf(v.z, sc, sh);
            v.w = fmaf(v.w, sc, sh);
            ((float4*)spA[s])[q] = v;
        }
        // ---- stage duplicated weights ----
        for (int i = tid; i < 12 * 81; i += 128) {
            const int j = i / 81, r = i - j * 81;
            const int s = r / 9, tap = r - s * 9;
            const float w = W2[((g * 12 + j) * CMID + ci) * 81 + r];
            wsm[(j * 9 + s) * 10 + tap] = make_float2(w, w);
        }
        __syncthreads();

        if (active) {
#pragma unroll
            for (int s = 0; s < 9; s++) {
                u64 a0[3], a1[3], a2[3], b0[3], b1[3];
#pragma unroll
                for (int kh = 0; kh < 3; kh++) {
                    const float2* rp = (const float2*)&spA[s][(ty + kh) * S1 + c];
                    const float2 f0 = rp[0], f1 = rp[1], f2 = rp[2];
                    a0[kh] = pack2(f0.x, f0.y);
                    a1[kh] = pack2(f1.x, f1.y);
                    a2[kh] = pack2(f2.x, f2.y);
                    b0[kh] = pack2(f0.y, f1.x);
                    b1[kh] = pack2(f1.y, f2.x);
                }
#pragma unroll
                for (int j = 0; j < 12; j++) {
                    const float2* wb = &wsm[(j * 9 + s) * 10];
                    const ulonglong2 w01 = *(const ulonglong2*)(wb + 0);
                    const ulonglong2 w23 = *(const ulonglong2*)(wb + 2);
                    const ulonglong2 w45 = *(const ulonglong2*)(wb + 4);
                    const ulonglong2 w67 = *(const ulonglong2*)(wb + 6);
                    const u64 w8 = *(const u64*)(wb + 8);
                    const u64 w[9] = {w01.x, w01.y, w23.x, w23.y,
                                      w45.x, w45.y, w67.x, w67.y, w8};
#pragma unroll
                    for (int kh = 0; kh < 3; kh++) {
                        ffma2(acc0[j], w[kh * 3 + 0], a0[kh], acc0[j]);
                        ffma2(acc1[j], w[kh * 3 + 0], a1[kh], acc1[j]);
                        ffma2(acc0[j], w[kh * 3 + 1], b0[kh], acc0[j]);
                        ffma2(acc1[j], w[kh * 3 + 1], b1[kh], acc1[j]);
                        ffma2(acc0[j], w[kh * 3 + 2], a1[kh], acc0[j]);
                        ffma2(acc1[j], w[kh * 3 + 2], a2[kh], acc1[j]);
                    }
                }
            }
        }
    }

    if (active) {
#pragma unroll
        for (int j = 0; j < 12; j++) {
            const int o = g * 12 + j;
            const float bo = b2[o];
            const int obase = ((b * COUT + o) * T2 + t) * (S2 * S2 * S2)
                            + d * (S2 * S2) + ty * S2 + c;
            out[obase + 0] = fmaxf(lo32(acc0[j]) + bo, 0.0f);
            out[obase + 1] = fmaxf(hi32(acc0[j]) + bo, 0.0f);
            out[obase + 2] = fmaxf(lo32(acc1[j]) + bo, 0.0f);
            out[obase + 3] = fmaxf(hi32(acc1[j]) + bo, 0.0f);
        }
    }
}

// ---------------------------------------------------------------------------
extern "C" void kernel_launch(void* const* d_in, const int* in_sizes, int n_in,
                              void* d_out, int out_size) {
    const float* x     = (const float*)d_in[0];
    const float* W1    = (const float*)d_in[1];
    const float* b1    = (const float*)d_in[2];
    const float* gamma = (const float*)d_in[3];
    const float* beta  = (const float*)d_in[4];
    const float* W2    = (const float*)d_in[5];
    const float* b2    = (const float*)d_in[6];
    float* out = (float*)d_out;

    zero_stats_k<<<1, 32>>>();
    conv1_k<<<dim3(S1, T1, B), 256>>>(x, W1, b1);
    finalize_k<<<1, 32>>>(gamma, beta);
    conv2_k<<<dim3(S2, T2, B * 3), 128>>>(W2, b2, out);
}

// round 5
// speedup vs baseline: 1.2933x; 1.1922x over previous
#include <cuda_runtime.h>

#define EPS 1e-3f
#define B    8
#define CIN  4
#define T0   20
#define S0   24
#define CMID 12
#define T1   18
#define S1   22
#define COUT 36
#define T2   16
#define S2   20

#define X_TOTAL (B*CIN*T0*S0*S0*S0)
#define H_TOTAL (B*CMID*T1*S1*S1*S1)

typedef unsigned long long u64;

__device__ float g_h[H_TOTAL];
__device__ float g_stats[24];
__device__ float g_scale[CMID];
__device__ float g_shift[CMID];

__device__ __forceinline__ void ffma2(u64& d, u64 a, u64 b, u64 c) {
    asm("fma.rn.f32x2 %0, %1, %2, %3;" : "=l"(d) : "l"(a), "l"(b), "l"(c));
}
__device__ __forceinline__ float lo32(u64 v){ return __uint_as_float((unsigned)v); }
__device__ __forceinline__ float hi32(u64 v){ return __uint_as_float((unsigned)(v>>32)); }

extern __shared__ float2 dynsm[];

// ---------------------------------------------------------------------------
__global__ void zero_stats_k() {
    if (threadIdx.x < 24) g_stats[threadIdx.x] = 0.0f;
}

// ---------------------------------------------------------------------------
// conv1 + ReLU + stats.  Block = (b,t,d) 22x22 plane, all 12 channels.
// Thread: 3 ch x 2 rows x 2 pairs (4 px).  Dual smem copy (aligned+shifted),
// no pack MOVs.  264 active threads of 288.
__global__ void __launch_bounds__(288, 2) conv1_k(const float* __restrict__ x,
                                                  const float* __restrict__ W1,
                                                  const float* __restrict__ b1) {
    float2* A  = dynsm;            // 9 subplanes x 24 rows x 12 float2 = 2592
    float2* Sh = A + 2592;         // shifted copy
    float2* Wm = Sh + 2592;        // 12j x 9s x 10 slots = 1080
    float*  sred = (float*)(Wm + 1080);   // 24

    const int d = blockIdx.x, t = blockIdx.y, b = blockIdx.z;
    const int tid = threadIdx.x;
    const bool act = tid < 264;
    const int cg = tid / 66;            // 0..3 (may be 4 for inactive tail)
    const int sp = tid - cg * 66;
    const int ry = sp / 6;              // 0..10
    const int tx = sp - ry * 6;         // 0..5 (tx==5: second pair masked)

    u64 acc[3][2][2];
#pragma unroll
    for (int a0 = 0; a0 < 3; a0++)
#pragma unroll
        for (int r = 0; r < 2; r++) { acc[a0][r][0] = 0ull; acc[a0][r][1] = 0ull; }
    if (tid < 24) sred[tid] = 0.0f;

    for (int ci = 0; ci < CIN; ci++) {
        __syncthreads();
        // stage 9 subplanes: 1296 float4 tasks, build aligned + shifted copies
#pragma unroll
        for (int k = 0; k < 5; k++) {
            const int i = tid + k * 288;
            if (i < 1296) {
                const int s = i / 144, q = i - s * 144;
                const int kt = s / 3, kd = s - 3 * kt;
                const int base = ((b*CIN + ci)*T0 + (t+kt))*(S0*S0*S0)
                               + (d + kd)*(S0*S0) + 4*q;
                float4 v = *(const float4*)(x + base);
                int ni = base + 4; if (ni > X_TOTAL - 1) ni = X_TOTAL - 1;
                const float nx = x[ni];
                ((float4*)A)[s*144 + q]  = v;
                ((float4*)Sh)[s*144 + q] = make_float4(v.y, v.z, v.w, nx);
            }
        }
        // stage duplicated weights: 972 tasks
#pragma unroll
        for (int k = 0; k < 4; k++) {
            const int i = tid + k * 288;
            if (i < 972) {
                const int j = i / 81, r = i - 81*j;
                const int s = r / 9, tap = r - 9*s;
                const float w = W1[(j*CIN + ci)*81 + r];
                Wm[(j*9 + s)*10 + tap] = make_float2(w, w);
            }
        }
        __syncthreads();

        if (act) {
            for (int s = 0; s < 9; s++) {
                u64 pa[4][3], pb[4][2];
#pragma unroll
                for (int lr = 0; lr < 4; lr++) {
                    const int ib = s*288 + (2*ry + lr)*12 + 2*tx;
                    const ulonglong2 t0 = *(const ulonglong2*)&A[ib];
                    pa[lr][0] = t0.x; pa[lr][1] = t0.y;
                    pa[lr][2] = *(const u64*)&A[ib + 2];
                    const ulonglong2 t1 = *(const ulonglong2*)&Sh[ib];
                    pb[lr][0] = t1.x; pb[lr][1] = t1.y;
                }
#pragma unroll
                for (int jj = 0; jj < 3; jj++) {
                    const int j = cg*3 + jj;
                    const float2* wb = &Wm[(j*9 + s)*10];
                    const ulonglong2 w01 = *(const ulonglong2*)(wb + 0);
                    const ulonglong2 w23 = *(const ulonglong2*)(wb + 2);
                    const ulonglong2 w45 = *(const ulonglong2*)(wb + 4);
                    const ulonglong2 w67 = *(const ulonglong2*)(wb + 6);
                    const u64 w8 = *(const u64*)(wb + 8);
                    const u64 w[9] = {w01.x, w01.y, w23.x, w23.y,
                                      w45.x, w45.y, w67.x, w67.y, w8};
#pragma unroll
                    for (int kh = 0; kh < 3; kh++)
#pragma unroll
                        for (int r = 0; r < 2; r++) {
                            ffma2(acc[jj][r][0], w[3*kh+0], pa[r+kh][0], acc[jj][r][0]);
                            ffma2(acc[jj][r][0], w[3*kh+1], pb[r+kh][0], acc[jj][r][0]);
                            ffma2(acc[jj][r][0], w[3*kh+2], pa[r+kh][1], acc[jj][r][0]);
                            ffma2(acc[jj][r][1], w[3*kh+0], pa[r+kh][1], acc[jj][r][1]);
                            ffma2(acc[jj][r][1], w[3*kh+1], pb[r+kh][1], acc[jj][r][1]);
                            ffma2(acc[jj][r][1], w[3*kh+2], pa[r+kh][2], acc[jj][r][1]);
                        }
                }
            }
        }
    }

    // epilogue: bias + relu + store + stats
    if (act) {
#pragma unroll
        for (int jj = 0; jj < 3; jj++) {
            const int j = cg*3 + jj;
            const float bj = b1[j];
            float s_ = 0.0f, q_ = 0.0f;
#pragma unroll
            for (int r = 0; r < 2; r++)
#pragma unroll
                for (int p = 0; p < 2; p++) {
                    if (tx == 5 && p == 1) continue;
                    const float v0 = fmaxf(lo32(acc[jj][r][p]) + bj, 0.0f);
                    const float v1 = fmaxf(hi32(acc[jj][r][p]) + bj, 0.0f);
                    const int hb = ((b*CMID + j)*T1 + t)*(S1*S1*S1)
                                 + d*(S1*S1) + (2*ry + r)*S1 + 4*tx + 2*p;
                    *(float2*)&g_h[hb] = make_float2(v0, v1);
                    s_ += v0 + v1;
                    q_ += v0*v0 + v1*v1;
                }
            atomicAdd(&sred[j], s_);
            atomicAdd(&sred[12 + j], q_);
        }
    }
    __syncthreads();
    if (tid < 24) atomicAdd(&g_stats[tid], sred[tid]);
}

// ---------------------------------------------------------------------------
__global__ void finalize_k(const float* __restrict__ gamma,
                           const float* __restrict__ beta) {
    const int tid = threadIdx.x;
    if (tid < CMID) {
        const float N = (float)(B * T1 * S1 * S1 * S1);
        const float mean = g_stats[tid] / N;
        const float var  = g_stats[12 + tid] / N - mean * mean;
        const float inv  = rsqrtf(var + EPS);
        const float sc   = gamma[tid] * inv;
        g_scale[tid] = sc;
        g_shift[tid] = beta[tid] - mean * sc;
    }
}

// ---------------------------------------------------------------------------
// conv2 + ReLU, bn folded into staging.  Block = (b,t,d) 20x20 plane, ALL 36
// channels.  Thread: 4 ch x 2 rows x 2 pairs.  450 active of 480.
__global__ void __launch_bounds__(480, 1) conv2_k(const float* __restrict__ W2,
                                                  const float* __restrict__ b2,
                                                  float* __restrict__ out) {
    float2* A  = dynsm;            // 9 x 22 rows x 12 float2 = 2376
    float2* Sh = A + 2376;
    float2* Wm = Sh + 2376;        // 36j x 9s x 10 = 3240
    float*  ssc = (float*)(Wm + 3240);   // 12 scale + 12 shift

    const int d = blockIdx.x, t = blockIdx.y, b = blockIdx.z;
    const int tid = threadIdx.x;
    const bool act = tid < 450;
    const int cg = tid / 50;            // 0..8
    const int sp = tid - cg * 50;
    const int ry = sp / 5;              // 0..9
    const int tx = sp - ry * 5;         // 0..4

    if (tid < CMID) { ssc[tid] = g_scale[tid]; ssc[12 + tid] = g_shift[tid]; }

    u64 acc[4][2][2];
#pragma unroll
    for (int a0 = 0; a0 < 4; a0++)
#pragma unroll
        for (int r = 0; r < 2; r++) { acc[a0][r][0] = 0ull; acc[a0][r][1] = 0ull; }

    for (int ci = 0; ci < CMID; ci++) {
        __syncthreads();
        const float sc = ssc[ci], shv = ssc[12 + ci];
        // stage 9 subplanes (22 rows x 11 valid float2, padded stride 12)
#pragma unroll
        for (int k = 0; k < 5; k++) {
            const int i = tid + k * 480;
            if (i < 2178) {
                const int s = i / 242, rem = i - 242*s;
                const int rr = rem / 11, p = rem - 11*rr;
                const int kt = s / 3, kd = s - 3*kt;
                const int base = ((b*CMID + ci)*T1 + (t+kt))*(S1*S1*S1)
                               + (d + kd)*(S1*S1) + rr*S1 + 2*p;
                const float2 v = *(const float2*)(g_h + base);
                int ni = base + 2; if (ni > H_TOTAL - 1) ni = H_TOTAL - 1;
                const float nx = g_h[ni];
                const float e0 = fmaf(v.x, sc, shv);
                const float e1 = fmaf(v.y, sc, shv);
                const float e2 = fmaf(nx,  sc, shv);
                A[s*264 + rr*12 + p]  = make_float2(e0, e1);
                Sh[s*264 + rr*12 + p] = make_float2(e1, e2);
            }
        }
        // stage duplicated weights: 36*81 = 2916 tasks
#pragma unroll
        for (int k = 0; k < 7; k++) {
            const int i = tid + k * 480;
            if (i < 2916) {
                const int j = i / 81, r = i - 81*j;
                const int s = r / 9, tap = r - 9*s;
                const float w = W2[(j*CMID + ci)*81 + r];
                Wm[(j*9 + s)*10 + tap] = make_float2(w, w);
            }
        }
        __syncthreads();

        if (act) {
            for (int s = 0; s < 9; s++) {
                u64 pa[4][3], pb[4][2];
#pragma unroll
                for (int lr = 0; lr < 4; lr++) {
                    const int ib = s*264 + (2*ry + lr)*12 + 2*tx;
                    const ulonglong2 t0 = *(const ulonglong2*)&A[ib];
                    pa[lr][0] = t0.x; pa[lr][1] = t0.y;
                    pa[lr][2] = *(const u64*)&A[ib + 2];
                    const ulonglong2 t1 = *(const ulonglong2*)&Sh[ib];
                    pb[lr][0] = t1.x; pb[lr][1] = t1.y;
                }
#pragma unroll
                for (int jj = 0; jj < 4; jj++) {
                    const int j = cg*4 + jj;
                    const float2* wb = &Wm[(j*9 + s)*10];
                    const ulonglong2 w01 = *(const ulonglong2*)(wb + 0);
                    const ulonglong2 w23 = *(const ulonglong2*)(wb + 2);
                    const ulonglong2 w45 = *(const ulonglong2*)(wb + 4);
                    const ulonglong2 w67 = *(const ulonglong2*)(wb + 6);
                    const u64 w8 = *(const u64*)(wb + 8);
                    const u64 w[9] = {w01.x, w01.y, w23.x, w23.y,
                                      w45.x, w45.y, w67.x, w67.y, w8};
#pragma unroll
                    for (int kh = 0; kh < 3; kh++)
#pragma unroll
                        for (int r = 0; r < 2; r++) {
                            ffma2(acc[jj][r][0], w[3*kh+0], pa[r+kh][0], acc[jj][r][0]);
                            ffma2(acc[jj][r][0], w[3*kh+1], pb[r+kh][0], acc[jj][r][0]);
                            ffma2(acc[jj][r][0], w[3*kh+2], pa[r+kh][1], acc[jj][r][0]);
                            ffma2(acc[jj][r][1], w[3*kh+0], pa[r+kh][1], acc[jj][r][1]);
                            ffma2(acc[jj][r][1], w[3*kh+1], pb[r+kh][1], acc[jj][r][1]);
                            ffma2(acc[jj][r][1], w[3*kh+2], pa[r+kh][2], acc[jj][r][1]);
                        }
                }
            }
        }
    }

    if (act) {
#pragma unroll
        for (int jj = 0; jj < 4; jj++) {
            const int j = cg*4 + jj;
            const float bo = b2[j];
#pragma unroll
            for (int r = 0; r < 2; r++) {
                const int obase = ((b*COUT + j)*T2 + t)*(S2*S2*S2)
                                + d*(S2*S2) + (2*ry + r)*S2 + 4*tx;
                float4 o;
                o.x = fmaxf(lo32(acc[jj][r][0]) + bo, 0.0f);
                o.y = fmaxf(hi32(acc[jj][r][0]) + bo, 0.0f);
                o.z = fmaxf(lo32(acc[jj][r][1]) + bo, 0.0f);
                o.w = fmaxf(hi32(acc[jj][r][1]) + bo, 0.0f);
                *(float4*)&out[obase] = o;
            }
        }
    }
}

// ---------------------------------------------------------------------------
extern "C" void kernel_launch(void* const* d_in, const int* in_sizes, int n_in,
                              void* d_out, int out_size) {
    const float* x     = (const float*)d_in[0];
    const float* W1    = (const float*)d_in[1];
    const float* b1    = (const float*)d_in[2];
    const float* gamma = (const float*)d_in[3];
    const float* beta  = (const float*)d_in[4];
    const float* W2    = (const float*)d_in[5];
    const float* b2    = (const float*)d_in[6];
    float* out = (float*)d_out;

    const int smem1 = (2592*2 + 1080) * 8 + 24 * 4;   // 50208 B
    const int smem2 = (2376*2 + 3240) * 8 + 24 * 4;   // 64032 B
    cudaFuncSetAttribute(conv1_k, cudaFuncAttributeMaxDynamicSharedMemorySize, smem1);
    cudaFuncSetAttribute(conv2_k, cudaFuncAttributeMaxDynamicSharedMemorySize, smem2);

    zero_stats_k<<<1, 32>>>();
    conv1_k<<<dim3(S1, T1, B), 288, smem1>>>(x, W1, b1);
    finalize_k<<<1, 32>>>(gamma, beta);
    conv2_k<<<dim3(S2, T2, B * 3 / 3), 480, smem2>>>(W2, b2, out);
}